// round 1
// baseline (speedup 1.0000x reference)
#include <cuda_runtime.h>
#include <math.h>

#define N_NODES 50000
#define NFEAT   64
#define NHID    64
#define E_REAL  200000
#define E_NHOP  40000
#define E_ALL   240000
#define N_REL   200
#define OUTF    128
#define ALPHA   0.2f

// ---------------- device scratch (static, no allocation) ----------------
// layer-1: 4 combos = (dir<<1)|head ; dir 0 = "in" (segment by edge[0]), 1 = "out" (reversed)
__device__ __align__(16) float g_P1[4][2][(size_t)N_NODES * 64];   // node projections (src-role, dst-role)
__device__ __align__(16) float g_Q1[4][(size_t)E_REAL * 64];       // per-edge edge-embed projections (real edges)
__device__ __align__(16) float g_R1proj[4][N_REL * 64];            // per-relation edge-embed projections (nhop)
__device__ __align__(16) float g_rel2[N_REL * OUTF];               // out_relation_1
__device__ __align__(16) float g_R2proj[N_REL * OUTF];             // rel2 @ a_o_edgepart^T
__device__ float g_rowsum1[4][N_NODES];
__device__ __align__(16) float g_hp1[4][(size_t)N_NODES * 64];
__device__ __align__(16) float g_xs[2][(size_t)N_NODES * OUTF];    // x_s1, x_s2
__device__ __align__(16) float g_P2[2][2][(size_t)N_NODES * OUTF]; // [xs][role]
__device__ float g_rowsum2[2][N_NODES];
__device__ __align__(16) float g_hp2[2][(size_t)N_NODES * OUTF];
__device__ __align__(16) float g_y[2][(size_t)N_NODES * OUTF];     // elu'd layer-2 outputs
__device__ float g_wsum[2];
__device__ float g_beta[2];

// ---------------- zero accumulators ----------------
__global__ void zero_accum() {
    size_t stride = (size_t)gridDim.x * blockDim.x;
    size_t i0 = (size_t)blockIdx.x * blockDim.x + threadIdx.x;
    float* hp1 = &g_hp1[0][0];
    float* hp2 = &g_hp2[0][0];
    for (size_t i = i0; i < (size_t)4 * N_NODES * 64; i += stride) hp1[i] = 0.f;
    for (size_t i = i0; i < (size_t)2 * N_NODES * OUTF; i += stride) hp2[i] = 0.f;
    float* rs1 = &g_rowsum1[0][0];
    float* rs2 = &g_rowsum2[0][0];
    for (size_t i = i0; i < (size_t)4 * N_NODES; i += stride) rs1[i] = 0.f;
    for (size_t i = i0; i < (size_t)2 * N_NODES; i += stride) rs2[i] = 0.f;
    if (i0 < 2) g_wsum[i0] = 0.f;
}

// ---------------- small relation-table kernels ----------------
// out_relation_1 = relation_embed @ W   (200 x 128), also written to output tail
__global__ void k_rel2(const float* __restrict__ rel, const float* __restrict__ W,
                       float* __restrict__ out_tail) {
    int r = blockIdx.x, j = threadIdx.x;
    float acc = 0.f;
    #pragma unroll
    for (int k = 0; k < 64; k++) acc += rel[r * 64 + k] * W[k * 128 + j];
    g_rel2[r * 128 + j] = acc;
    out_tail[(size_t)N_NODES * OUTF + r * 128 + j] = acc;
}

// R2proj[r][j] = sum_k rel2[r][k] * a_o[j][256+k]
__global__ void k_r2proj(const float* __restrict__ a_o) {
    int r = blockIdx.x, j = threadIdx.x;
    float acc = 0.f;
    #pragma unroll
    for (int k = 0; k < 128; k++) acc += g_rel2[r * 128 + k] * a_o[j * 384 + 256 + k];
    g_R2proj[r * 128 + j] = acc;
}

// R1proj[c][r][j] = sum_k rel[r][k] * a_c[j][128+k]
__global__ void k_r1proj(const float* __restrict__ rel, const float* __restrict__ a_in,
                         const float* __restrict__ a_out) {
    int r = blockIdx.x;
    int c = threadIdx.x >> 6;
    int j = threadIdx.x & 63;
    const float* A = ((c >> 1) ? a_out : a_in) + (size_t)(c & 1) * 64 * 192;
    float acc = 0.f;
    #pragma unroll
    for (int k = 0; k < 64; k++) acc += rel[r * 64 + k] * A[j * 192 + 128 + k];
    g_R1proj[c][r * 64 + j] = acc;
}

// ---------------- generic GEMM: C[i][jbase+j] = sum_k X[i][k] * A[(jbase+j)*lda + koff + k]
// 128 threads, 64x64 output tile, register tile 4j x 8i
__global__ void gemm_xt(const float* __restrict__ X, int ldx,
                        const float* __restrict__ A, int lda, int koff,
                        float* __restrict__ C, int ldc, int jbase,
                        int M, int K) {
    __shared__ float Ast[64][65];  // [k][j]
    __shared__ float Xs[64][65];   // [i][k]
    int t = threadIdx.x;
    int ibase = blockIdx.x * 64;
    int jq = t & 15;
    int iq = t >> 4;  // 0..7
    float acc[8][4];
    #pragma unroll
    for (int ii = 0; ii < 8; ii++)
        #pragma unroll
        for (int x = 0; x < 4; x++) acc[ii][x] = 0.f;

    for (int kc = 0; kc < K; kc += 64) {
        for (int p = t; p < 4096; p += 128) {
            int j = p >> 6, kk = p & 63;
            Ast[kk][j] = A[(size_t)(jbase + j) * lda + koff + kc + kk];
        }
        for (int p = t; p < 4096; p += 128) {
            int i = p >> 6, kk = p & 63;
            int gi = ibase + i;
            Xs[i][kk] = (gi < M) ? X[(size_t)gi * ldx + kc + kk] : 0.f;
        }
        __syncthreads();
        #pragma unroll 8
        for (int kk = 0; kk < 64; kk++) {
            float av[4];
            #pragma unroll
            for (int x = 0; x < 4; x++) av[x] = Ast[kk][jq + 16 * x];
            #pragma unroll
            for (int ii = 0; ii < 8; ii++) {
                float xv = Xs[iq * 8 + ii][kk];
                #pragma unroll
                for (int x = 0; x < 4; x++) acc[ii][x] += xv * av[x];
            }
        }
        __syncthreads();
    }
    #pragma unroll
    for (int ii = 0; ii < 8; ii++) {
        int gi = ibase + iq * 8 + ii;
        if (gi < M) {
            #pragma unroll
            for (int x = 0; x < 4; x++)
                C[(size_t)gi * ldc + jbase + jq + 16 * x] = acc[ii][x];
        }
    }
}

// ---------------- layer-1 edge pass: one warp per (combo, edge) ----------------
__global__ void edge_pass1(const int* __restrict__ el, const int* __restrict__ eln,
                           const int* __restrict__ etn,
                           const float* __restrict__ a2_in, const float* __restrict__ a2_out) {
    int c = blockIdx.y;
    int e = blockIdx.x * 8 + (threadIdx.x >> 5);
    if (e >= E_ALL) return;
    int lane = threadIdx.x & 31;
    int dir = c >> 1, h = c & 1;
    int i0, i1;
    float qx, qy;
    if (e < E_REAL) {
        i0 = el[e]; i1 = el[E_REAL + e];
        float2 q2 = *(const float2*)&g_Q1[c][(size_t)e * 64 + 2 * lane];
        qx = q2.x; qy = q2.y;
    } else {
        int en = e - E_REAL;
        i0 = eln[en]; i1 = eln[E_NHOP + en];
        int t0 = etn[2 * en], t1 = etn[2 * en + 1];
        float2 qa = *(const float2*)&g_R1proj[c][t0 * 64 + 2 * lane];
        float2 qb = *(const float2*)&g_R1proj[c][t1 * 64 + 2 * lane];
        qx = qa.x + qb.x; qy = qa.y + qb.y;
    }
    int src = dir ? i1 : i0;   // segment node (edge[0] of this direction)
    int dst = dir ? i0 : i1;
    float2 p = *(const float2*)&g_P1[c][0][(size_t)src * 64 + 2 * lane];
    float2 d = *(const float2*)&g_P1[c][1][(size_t)dst * 64 + 2 * lane];
    float mx = p.x + d.x + qx;
    float my = p.y + d.y + qy;
    const float* a2 = (dir ? a2_out : a2_in) + h * 64;
    float part = mx * a2[2 * lane] + my * a2[2 * lane + 1];
    #pragma unroll
    for (int o = 16; o; o >>= 1) part += __shfl_xor_sync(0xffffffffu, part, o);
    float lk = part > 0.f ? part : ALPHA * part;
    float ev = expf(-lk);
    float* hp = &g_hp1[c][(size_t)src * 64 + 2 * lane];
    atomicAdd(hp, ev * mx);
    atomicAdd(hp + 1, ev * my);
    if (lane == 0) atomicAdd(&g_rowsum1[c][src], ev);
}

// ---------------- normalize + elu -> x_s ----------------
__global__ void norm1() {
    int c = blockIdx.y;
    int idx = blockIdx.x * 256 + threadIdx.x;
    if (idx >= N_NODES * 64) return;
    int i = idx >> 6, k = idx & 63;
    float rs = g_rowsum1[c][i];
    float v = g_hp1[c][idx];
    v = (rs > 0.f) ? v / rs : 0.f;
    v = (v > 0.f) ? v : expm1f(v);
    int dir = c >> 1, h = c & 1;
    g_xs[dir][(size_t)i * 128 + h * 64 + k] = v;
}

// ---------------- layer-2 edge pass: one warp per (dir, edge) ----------------
__global__ void edge_pass2(const int* __restrict__ el, const int* __restrict__ eln,
                           const int* __restrict__ et, const int* __restrict__ etn,
                           const float* __restrict__ a2_o) {
    int dir = blockIdx.y;
    int e = blockIdx.x * 8 + (threadIdx.x >> 5);
    if (e >= E_ALL) return;
    int lane = threadIdx.x & 31;
    int i0, i1;
    float q0, q1, q2, q3;
    if (e < E_REAL) {
        i0 = el[e]; i1 = el[E_REAL + e];
        int ty = et[e];
        float4 qv = *(const float4*)&g_R2proj[ty * 128 + 4 * lane];
        q0 = qv.x; q1 = qv.y; q2 = qv.z; q3 = qv.w;
    } else {
        int en = e - E_REAL;
        i0 = eln[en]; i1 = eln[E_NHOP + en];
        int t0 = etn[2 * en], t1 = etn[2 * en + 1];
        float4 qa = *(const float4*)&g_R2proj[t0 * 128 + 4 * lane];
        float4 qb = *(const float4*)&g_R2proj[t1 * 128 + 4 * lane];
        q0 = qa.x + qb.x; q1 = qa.y + qb.y; q2 = qa.z + qb.z; q3 = qa.w + qb.w;
    }
    int seg = dir ? i1 : i0;
    int nbr = dir ? i0 : i1;
    float4 pv = *(const float4*)&g_P2[dir][0][(size_t)seg * 128 + 4 * lane];
    float4 dv = *(const float4*)&g_P2[dir][1][(size_t)nbr * 128 + 4 * lane];
    float m0 = pv.x + dv.x + q0;
    float m1 = pv.y + dv.y + q1;
    float m2 = pv.z + dv.z + q2;
    float m3 = pv.w + dv.w + q3;
    float4 av = *(const float4*)&a2_o[4 * lane];
    float part = m0 * av.x + m1 * av.y + m2 * av.z + m3 * av.w;
    #pragma unroll
    for (int o = 16; o; o >>= 1) part += __shfl_xor_sync(0xffffffffu, part, o);
    float lk = part > 0.f ? part : ALPHA * part;
    float ev = expf(-lk);
    float* hp = &g_hp2[dir][(size_t)seg * 128 + 4 * lane];
    atomicAdd(hp + 0, ev * m0);
    atomicAdd(hp + 1, ev * m1);
    atomicAdd(hp + 2, ev * m2);
    atomicAdd(hp + 3, ev * m3);
    if (lane == 0) atomicAdd(&g_rowsum2[dir][seg], ev);
}

// ---------------- layer-2 normalize + elu + attention scores ----------------
__global__ void node_final1(const float* __restrict__ We, const float* __restrict__ be,
                            const float* __restrict__ qe) {
    int xs = blockIdx.y;
    int w = threadIdx.x >> 5;
    int lane = threadIdx.x & 31;
    int node = blockIdx.x * 8 + w;
    if (node >= N_NODES) return;
    __shared__ float ysm[8][128];
    float rs = g_rowsum2[xs][node];
    float inv = (rs > 0.f) ? 1.f / rs : 0.f;
    #pragma unroll
    for (int u = 0; u < 4; u++) {
        int k = 4 * lane + u;
        float v = g_hp2[xs][(size_t)node * 128 + k] * inv;
        v = (v > 0.f) ? v : expm1f(v);
        ysm[w][k] = v;
        g_y[xs][(size_t)node * 128 + k] = v;
    }
    __syncwarp();
    float wp = 0.f;
    #pragma unroll
    for (int half = 0; half < 2; half++) {
        int j = lane + 32 * half;
        float acc = be[j];
        #pragma unroll 8
        for (int k = 0; k < 128; k++) acc += ysm[w][k] * We[k * 64 + j];
        wp += tanhf(acc) * qe[j];
    }
    #pragma unroll
    for (int o = 16; o; o >>= 1) wp += __shfl_xor_sync(0xffffffffu, wp, o);
    if (lane == 0) atomicAdd(&g_wsum[xs], wp);
}

__global__ void calc_beta() {
    float m0 = g_wsum[0] / (float)N_NODES;
    float m1 = g_wsum[1] / (float)N_NODES;
    float mx = fmaxf(m0, m1);
    float e0 = expf(m0 - mx), e1 = expf(m1 - mx);
    float s = e0 + e1;
    g_beta[0] = e0 / s;
    g_beta[1] = e1 / s;
}

__global__ void combine(float* __restrict__ out) {
    size_t i = (size_t)blockIdx.x * 256 + threadIdx.x;
    if (i >= (size_t)N_NODES * OUTF) return;
    out[i] = g_beta[0] * g_y[0][i] + g_beta[1] * g_y[1][i];
}

// ---------------- launch ----------------
extern "C" void kernel_launch(void* const* d_in, const int* in_sizes, int n_in,
                              void* d_out, int out_size) {
    const float* ent   = (const float*)d_in[0];
    const float* rel   = (const float*)d_in[1];
    const int*   el    = (const int*)d_in[2];
    const int*   et    = (const int*)d_in[3];
    const float* eemb  = (const float*)d_in[4];
    const int*   eln   = (const int*)d_in[5];
    const int*   etn   = (const int*)d_in[6];
    const float* a_in  = (const float*)d_in[7];
    const float* a2_in = (const float*)d_in[8];
    const float* a_out = (const float*)d_in[9];
    const float* a2_out= (const float*)d_in[10];
    const float* a_o   = (const float*)d_in[11];
    const float* a2_o  = (const float*)d_in[12];
    const float* W     = (const float*)d_in[13];
    const float* We    = (const float*)d_in[14];
    const float* be    = (const float*)d_in[15];
    const float* qe    = (const float*)d_in[16];
    float* out = (float*)d_out;

    float *p1 = 0, *q1 = 0, *xsb = 0, *p2 = 0;
    cudaGetSymbolAddress((void**)&p1, g_P1);
    cudaGetSymbolAddress((void**)&q1, g_Q1);
    cudaGetSymbolAddress((void**)&xsb, g_xs);
    cudaGetSymbolAddress((void**)&p2, g_P2);

    zero_accum<<<4096, 256>>>();
    k_rel2<<<200, 128>>>(rel, W, out);
    k_r2proj<<<200, 128>>>(a_o);
    k_r1proj<<<200, 256>>>(rel, a_in, a_out);

    // layer-1 node + edge projections
    for (int c = 0; c < 4; c++) {
        const float* A = ((c >> 1) ? a_out : a_in) + (size_t)(c & 1) * 64 * 192;
        for (int role = 0; role < 2; role++) {
            gemm_xt<<<(N_NODES + 63) / 64, 128>>>(
                ent, 64, A, 192, role * 64,
                p1 + (size_t)(c * 2 + role) * N_NODES * 64, 64, 0, N_NODES, 64);
        }
        gemm_xt<<<(E_REAL + 63) / 64, 128>>>(
            eemb, 64, A, 192, 128,
            q1 + (size_t)c * E_REAL * 64, 64, 0, E_REAL, 64);
    }

    edge_pass1<<<dim3(E_ALL / 8, 4), 256>>>(el, eln, etn, a2_in, a2_out);
    norm1<<<dim3((N_NODES * 64 + 255) / 256, 4), 256>>>();

    // layer-2 node projections
    for (int xs = 0; xs < 2; xs++)
        for (int role = 0; role < 2; role++)
            for (int jt = 0; jt < 2; jt++)
                gemm_xt<<<(N_NODES + 63) / 64, 128>>>(
                    xsb + (size_t)xs * N_NODES * 128, 128,
                    a_o, 384, role * 128,
                    p2 + (size_t)(xs * 2 + role) * N_NODES * 128, 128, jt * 64,
                    N_NODES, 128);

    edge_pass2<<<dim3(E_ALL / 8, 2), 256>>>(el, eln, et, etn, a2_o);
    node_final1<<<dim3((N_NODES + 7) / 8, 2), 256>>>(We, be, qe);
    calc_beta<<<1, 1>>>();
    combine<<<(N_NODES * OUTF + 255) / 256, 256>>>(out);
}

// round 2
// speedup vs baseline: 1.2475x; 1.2475x over previous
#include <cuda_runtime.h>
#include <math.h>

#define N_NODES 50000
#define NFEAT   64
#define NHID    64
#define E_REAL  200000
#define E_NHOP  40000
#define E_ALL   240000
#define N_REL   200
#define OUTF    128
#define ALPHA   0.2f

// ---------------- device scratch (static, no allocation) ----------------
// combo c = (dir<<1)|head ; dir 0 = "in" (segment by edge[0]), 1 = "out" (reversed)
__device__ __align__(16) float g_P1all[(size_t)N_NODES * 512];     // [i][c*128 + role*64 + j]
__device__ __align__(16) float g_Q1all[(size_t)E_REAL * 256];      // [e][c*64 + j]
__device__ __align__(16) float g_R1proj[4][N_REL * 64];            // nhop relation projections
__device__ __align__(16) float g_rel2[N_REL * OUTF];               // out_relation_1
__device__ __align__(16) float g_R2proj[N_REL * OUTF];             // rel2 @ a_o_edgepart^T
__device__ float g_rowsum1[4][N_NODES];
__device__ __align__(16) float g_hp1[4][(size_t)N_NODES * 64];
__device__ __align__(16) float g_xs[2][(size_t)N_NODES * OUTF];    // x_s1, x_s2
__device__ __align__(16) float g_P2all[2][(size_t)N_NODES * 256];  // [xs][i][role*128 + j]
__device__ float g_rowsum2[2][N_NODES];
__device__ __align__(16) float g_hp2[2][(size_t)N_NODES * OUTF];
__device__ __align__(16) float g_y[2][(size_t)N_NODES * OUTF];
__device__ float g_wsum[2];
__device__ float g_beta[2];
// packed weights
__device__ __align__(16) float g_Wp1[512 * 64];
__device__ __align__(16) float g_WpQ[256 * 64];
__device__ __align__(16) float g_Wp2[256 * 128];

// vector reductions (Blackwell/Hopper PTX)
#define RED2(ptr, a, b) \
    asm volatile("red.global.add.v2.f32 [%0], {%1, %2};" :: "l"(ptr), "f"(a), "f"(b) : "memory")
#define RED4(ptr, a, b, c, d) \
    asm volatile("red.global.add.v4.f32 [%0], {%1, %2, %3, %4};" :: "l"(ptr), "f"(a), "f"(b), "f"(c), "f"(d) : "memory")

// ---------------- zero accumulators ----------------
__global__ void zero_accum() {
    size_t stride = (size_t)gridDim.x * blockDim.x;
    size_t i0 = (size_t)blockIdx.x * blockDim.x + threadIdx.x;
    float* hp1 = &g_hp1[0][0];
    float* hp2 = &g_hp2[0][0];
    for (size_t i = i0; i < (size_t)4 * N_NODES * 64; i += stride) hp1[i] = 0.f;
    for (size_t i = i0; i < (size_t)2 * N_NODES * OUTF; i += stride) hp2[i] = 0.f;
    float* rs1 = &g_rowsum1[0][0];
    float* rs2 = &g_rowsum2[0][0];
    for (size_t i = i0; i < (size_t)4 * N_NODES; i += stride) rs1[i] = 0.f;
    for (size_t i = i0; i < (size_t)2 * N_NODES; i += stride) rs2[i] = 0.f;
    if (i0 < 2) g_wsum[i0] = 0.f;
}

// ---------------- weight packing ----------------
__global__ void pack_all(const float* __restrict__ a_in, const float* __restrict__ a_out,
                         const float* __restrict__ a_o) {
    int r = blockIdx.x;
    int k = threadIdx.x;  // 128
    if (r < 512) {
        if (k < 64) {
            int c = r >> 7, rem = r & 127, role = rem >> 6, j = rem & 63;
            const float* A = ((c >> 1) ? a_out : a_in) + (size_t)(c & 1) * 64 * 192;
            g_Wp1[r * 64 + k] = A[j * 192 + role * 64 + k];
        }
    } else if (r < 768) {
        if (k < 64) {
            int rr = r - 512;
            int c = rr >> 6, j = rr & 63;
            const float* A = ((c >> 1) ? a_out : a_in) + (size_t)(c & 1) * 64 * 192;
            g_WpQ[rr * 64 + k] = A[j * 192 + 128 + k];
        }
    } else {
        int rr = r - 768;
        int role = rr >> 7, j = rr & 127;
        g_Wp2[rr * 128 + k] = a_o[j * 384 + role * 128 + k];
    }
}

// ---------------- small relation-table kernels ----------------
__global__ void k_rel2(const float* __restrict__ rel, const float* __restrict__ W,
                       float* __restrict__ out_tail) {
    int r = blockIdx.x, j = threadIdx.x;
    float acc = 0.f;
    #pragma unroll
    for (int k = 0; k < 64; k++) acc += rel[r * 64 + k] * W[k * 128 + j];
    g_rel2[r * 128 + j] = acc;
    out_tail[(size_t)N_NODES * OUTF + r * 128 + j] = acc;
}

__global__ void k_r2proj(const float* __restrict__ a_o) {
    int r = blockIdx.x, j = threadIdx.x;
    float acc = 0.f;
    #pragma unroll
    for (int k = 0; k < 128; k++) acc += g_rel2[r * 128 + k] * a_o[j * 384 + 256 + k];
    g_R2proj[r * 128 + j] = acc;
}

__global__ void k_r1proj(const float* __restrict__ rel, const float* __restrict__ a_in,
                         const float* __restrict__ a_out) {
    int r = blockIdx.x;
    int c = threadIdx.x >> 6;
    int j = threadIdx.x & 63;
    const float* A = ((c >> 1) ? a_out : a_in) + (size_t)(c & 1) * 64 * 192;
    float acc = 0.f;
    #pragma unroll
    for (int k = 0; k < 64; k++) acc += rel[r * 64 + k] * A[j * 192 + 128 + k];
    g_R1proj[c][r * 64 + j] = acc;
}

// ---------------- f32x2 packed GEMM ----------------
// C[i][jb+j] = sum_k X[i*K + k] * Wp[(jb+j)*K + k]
// block tile 128(M) x 128(N), K chunked by 32; 256 threads, 8x8 per-thread tile.
// Column pairing for FFMA2: pair pi = tx + 16*q holds columns (tx+32q, tx+32q+16).
__global__ void gemm_f32x2(const float* __restrict__ X,
                           const float* __restrict__ Wp,
                           float* __restrict__ C,
                           int M, int N, int K) {
    __shared__ float Xs[128][33];
    __shared__ float2 As2[32][65];
    int t = threadIdx.x;
    int tx = t & 15, ty = t >> 4;
    int ib = blockIdx.x * 128;
    int jb = blockIdx.y * 128;
    unsigned long long acc[8][4];
    #pragma unroll
    for (int ii = 0; ii < 8; ii++)
        #pragma unroll
        for (int q = 0; q < 4; q++) acc[ii][q] = 0ull;

    for (int kc = 0; kc < K; kc += 32) {
        // X tile: 128 rows x 32 cols, float4 loads
        #pragma unroll
        for (int p = t; p < 1024; p += 256) {
            int i = p >> 3, kq = (p & 7) * 4;
            int gi = ib + i;
            float4 v = make_float4(0.f, 0.f, 0.f, 0.f);
            if (gi < M) v = *(const float4*)&X[(size_t)gi * K + kc + kq];
            Xs[i][kq + 0] = v.x; Xs[i][kq + 1] = v.y;
            Xs[i][kq + 2] = v.z; Xs[i][kq + 3] = v.w;
        }
        // A tile: 128 rows (j) x 32 cols (k), transposed + paired into As2
        #pragma unroll
        for (int p = t; p < 1024; p += 256) {
            int j = p >> 3, kq = (p & 7) * 4;
            float4 v = *(const float4*)&Wp[(size_t)(jb + j) * K + kc + kq];
            int pi = (j & 15) + 16 * (j >> 5);
            if (j & 16) {
                As2[kq + 0][pi].y = v.x; As2[kq + 1][pi].y = v.y;
                As2[kq + 2][pi].y = v.z; As2[kq + 3][pi].y = v.w;
            } else {
                As2[kq + 0][pi].x = v.x; As2[kq + 1][pi].x = v.y;
                As2[kq + 2][pi].x = v.z; As2[kq + 3][pi].x = v.w;
            }
        }
        __syncthreads();
        #pragma unroll 8
        for (int kk = 0; kk < 32; kk++) {
            unsigned long long av[4];
            #pragma unroll
            for (int q = 0; q < 4; q++)
                av[q] = *(const unsigned long long*)&As2[kk][tx + 16 * q];
            #pragma unroll
            for (int ii = 0; ii < 8; ii++) {
                float xv = Xs[ty * 8 + ii][kk];
                unsigned long long xx;
                asm("mov.b64 %0, {%1, %1};" : "=l"(xx) : "f"(xv));
                #pragma unroll
                for (int q = 0; q < 4; q++)
                    asm("fma.rn.f32x2 %0, %1, %2, %0;"
                        : "+l"(acc[ii][q]) : "l"(xx), "l"(av[q]));
            }
        }
        __syncthreads();
    }
    #pragma unroll
    for (int ii = 0; ii < 8; ii++) {
        int gi = ib + ty * 8 + ii;
        if (gi < M) {
            #pragma unroll
            for (int q = 0; q < 4; q++) {
                float lo, hi;
                asm("mov.b64 {%0, %1}, %2;" : "=f"(lo), "=f"(hi) : "l"(acc[ii][q]));
                C[(size_t)gi * N + jb + tx + 32 * q] = lo;
                C[(size_t)gi * N + jb + tx + 32 * q + 16] = hi;
            }
        }
    }
}

// ---------------- layer-1 edge pass: one warp per (combo, edge) ----------------
__global__ void edge_pass1(const int* __restrict__ el, const int* __restrict__ eln,
                           const int* __restrict__ etn,
                           const float* __restrict__ a2_in, const float* __restrict__ a2_out) {
    int c = blockIdx.y;
    int e = blockIdx.x * 8 + (threadIdx.x >> 5);
    if (e >= E_ALL) return;
    int lane = threadIdx.x & 31;
    int dir = c >> 1, h = c & 1;
    int i0, i1;
    float qx, qy;
    if (e < E_REAL) {
        i0 = el[e]; i1 = el[E_REAL + e];
        float2 q2 = *(const float2*)&g_Q1all[(size_t)e * 256 + c * 64 + 2 * lane];
        qx = q2.x; qy = q2.y;
    } else {
        int en = e - E_REAL;
        i0 = eln[en]; i1 = eln[E_NHOP + en];
        int t0 = etn[2 * en], t1 = etn[2 * en + 1];
        float2 qa = *(const float2*)&g_R1proj[c][t0 * 64 + 2 * lane];
        float2 qb = *(const float2*)&g_R1proj[c][t1 * 64 + 2 * lane];
        qx = qa.x + qb.x; qy = qa.y + qb.y;
    }
    int src = dir ? i1 : i0;
    int dst = dir ? i0 : i1;
    float2 p = *(const float2*)&g_P1all[(size_t)src * 512 + c * 128 + 2 * lane];
    float2 d = *(const float2*)&g_P1all[(size_t)dst * 512 + c * 128 + 64 + 2 * lane];
    float mx = p.x + d.x + qx;
    float my = p.y + d.y + qy;
    const float* a2 = (dir ? a2_out : a2_in) + h * 64;
    float part = mx * a2[2 * lane] + my * a2[2 * lane + 1];
    #pragma unroll
    for (int o = 16; o; o >>= 1) part += __shfl_xor_sync(0xffffffffu, part, o);
    float lk = part > 0.f ? part : ALPHA * part;
    float ev = expf(-lk);
    float* hp = &g_hp1[c][(size_t)src * 64 + 2 * lane];
    RED2(hp, ev * mx, ev * my);
    if (lane == 0) atomicAdd(&g_rowsum1[c][src], ev);
}

// ---------------- normalize + elu -> x_s ----------------
__global__ void norm1() {
    int c = blockIdx.y;
    int idx = blockIdx.x * 256 + threadIdx.x;
    if (idx >= N_NODES * 64) return;
    int i = idx >> 6, k = idx & 63;
    float rs = g_rowsum1[c][i];
    float v = g_hp1[c][idx];
    v = (rs > 0.f) ? v / rs : 0.f;
    v = (v > 0.f) ? v : expm1f(v);
    int dir = c >> 1, h = c & 1;
    g_xs[dir][(size_t)i * 128 + h * 64 + k] = v;
}

// ---------------- layer-2 edge pass ----------------
__global__ void edge_pass2(const int* __restrict__ el, const int* __restrict__ eln,
                           const int* __restrict__ et, const int* __restrict__ etn,
                           const float* __restrict__ a2_o) {
    int dir = blockIdx.y;
    int e = blockIdx.x * 8 + (threadIdx.x >> 5);
    if (e >= E_ALL) return;
    int lane = threadIdx.x & 31;
    int i0, i1;
    float q0, q1, q2, q3;
    if (e < E_REAL) {
        i0 = el[e]; i1 = el[E_REAL + e];
        int ty = et[e];
        float4 qv = *(const float4*)&g_R2proj[ty * 128 + 4 * lane];
        q0 = qv.x; q1 = qv.y; q2 = qv.z; q3 = qv.w;
    } else {
        int en = e - E_REAL;
        i0 = eln[en]; i1 = eln[E_NHOP + en];
        int t0 = etn[2 * en], t1 = etn[2 * en + 1];
        float4 qa = *(const float4*)&g_R2proj[t0 * 128 + 4 * lane];
        float4 qb = *(const float4*)&g_R2proj[t1 * 128 + 4 * lane];
        q0 = qa.x + qb.x; q1 = qa.y + qb.y; q2 = qa.z + qb.z; q3 = qa.w + qb.w;
    }
    int seg = dir ? i1 : i0;
    int nbr = dir ? i0 : i1;
    float4 pv = *(const float4*)&g_P2all[dir][(size_t)seg * 256 + 4 * lane];
    float4 dv = *(const float4*)&g_P2all[dir][(size_t)nbr * 256 + 128 + 4 * lane];
    float m0 = pv.x + dv.x + q0;
    float m1 = pv.y + dv.y + q1;
    float m2 = pv.z + dv.z + q2;
    float m3 = pv.w + dv.w + q3;
    float4 av = *(const float4*)&a2_o[4 * lane];
    float part = m0 * av.x + m1 * av.y + m2 * av.z + m3 * av.w;
    #pragma unroll
    for (int o = 16; o; o >>= 1) part += __shfl_xor_sync(0xffffffffu, part, o);
    float lk = part > 0.f ? part : ALPHA * part;
    float ev = expf(-lk);
    float* hp = &g_hp2[dir][(size_t)seg * 128 + 4 * lane];
    RED4(hp, ev * m0, ev * m1, ev * m2, ev * m3);
    if (lane == 0) atomicAdd(&g_rowsum2[dir][seg], ev);
}

// ---------------- layer-2 normalize + elu + attention scores ----------------
__global__ void node_final1(const float* __restrict__ We, const float* __restrict__ be,
                            const float* __restrict__ qe) {
    int xs = blockIdx.y;
    int w = threadIdx.x >> 5;
    int lane = threadIdx.x & 31;
    int node = blockIdx.x * 8 + w;
    if (node >= N_NODES) return;
    __shared__ float ysm[8][128];
    float rs = g_rowsum2[xs][node];
    float inv = (rs > 0.f) ? 1.f / rs : 0.f;
    #pragma unroll
    for (int u = 0; u < 4; u++) {
        int k = 4 * lane + u;
        float v = g_hp2[xs][(size_t)node * 128 + k] * inv;
        v = (v > 0.f) ? v : expm1f(v);
        ysm[w][k] = v;
        g_y[xs][(size_t)node * 128 + k] = v;
    }
    __syncwarp();
    float wp = 0.f;
    #pragma unroll
    for (int half = 0; half < 2; half++) {
        int j = lane + 32 * half;
        float acc = be[j];
        #pragma unroll 8
        for (int k = 0; k < 128; k++) acc += ysm[w][k] * We[k * 64 + j];
        wp += tanhf(acc) * qe[j];
    }
    #pragma unroll
    for (int o = 16; o; o >>= 1) wp += __shfl_xor_sync(0xffffffffu, wp, o);
    if (lane == 0) atomicAdd(&g_wsum[xs], wp);
}

__global__ void calc_beta() {
    float m0 = g_wsum[0] / (float)N_NODES;
    float m1 = g_wsum[1] / (float)N_NODES;
    float mx = fmaxf(m0, m1);
    float e0 = expf(m0 - mx), e1 = expf(m1 - mx);
    float s = e0 + e1;
    g_beta[0] = e0 / s;
    g_beta[1] = e1 / s;
}

__global__ void combine(float* __restrict__ out) {
    size_t i = (size_t)blockIdx.x * 256 + threadIdx.x;
    if (i >= (size_t)N_NODES * OUTF) return;
    out[i] = g_beta[0] * g_y[0][i] + g_beta[1] * g_y[1][i];
}

// ---------------- launch ----------------
extern "C" void kernel_launch(void* const* d_in, const int* in_sizes, int n_in,
                              void* d_out, int out_size) {
    const float* ent   = (const float*)d_in[0];
    const float* rel   = (const float*)d_in[1];
    const int*   el    = (const int*)d_in[2];
    const int*   et    = (const int*)d_in[3];
    const float* eemb  = (const float*)d_in[4];
    const int*   eln   = (const int*)d_in[5];
    const int*   etn   = (const int*)d_in[6];
    const float* a_in  = (const float*)d_in[7];
    const float* a2_in = (const float*)d_in[8];
    const float* a_out = (const float*)d_in[9];
    const float* a2_out= (const float*)d_in[10];
    const float* a_o   = (const float*)d_in[11];
    const float* a2_o  = (const float*)d_in[12];
    const float* W     = (const float*)d_in[13];
    const float* We    = (const float*)d_in[14];
    const float* be    = (const float*)d_in[15];
    const float* qe    = (const float*)d_in[16];
    float* out = (float*)d_out;

    float *p1 = 0, *q1 = 0, *xsb = 0, *p2 = 0, *wp1 = 0, *wpq = 0, *wp2 = 0;
    cudaGetSymbolAddress((void**)&p1, g_P1all);
    cudaGetSymbolAddress((void**)&q1, g_Q1all);
    cudaGetSymbolAddress((void**)&xsb, g_xs);
    cudaGetSymbolAddress((void**)&p2, g_P2all);
    cudaGetSymbolAddress((void**)&wp1, g_Wp1);
    cudaGetSymbolAddress((void**)&wpq, g_WpQ);
    cudaGetSymbolAddress((void**)&wp2, g_Wp2);

    zero_accum<<<4096, 256>>>();
    pack_all<<<1024, 128>>>(a_in, a_out, a_o);
    k_rel2<<<200, 128>>>(rel, W, out);
    k_r2proj<<<200, 128>>>(a_o);
    k_r1proj<<<200, 256>>>(rel, a_in, a_out);

    // layer-1 projections: one N=512 GEMM (node) + one N=256 GEMM (edge-embed)
    gemm_f32x2<<<dim3((N_NODES + 127) / 128, 4), 256>>>(ent, wp1, p1, N_NODES, 512, 64);
    gemm_f32x2<<<dim3((E_REAL + 127) / 128, 2), 256>>>(eemb, wpq, q1, E_REAL, 256, 64);

    edge_pass1<<<dim3(E_ALL / 8, 4), 256>>>(el, eln, etn, a2_in, a2_out);
    norm1<<<dim3((N_NODES * 64 + 255) / 256, 4), 256>>>();

    // layer-2 projections: two N=256 GEMMs (K=128)
    for (int xs = 0; xs < 2; xs++)
        gemm_f32x2<<<dim3((N_NODES + 127) / 128, 2), 256>>>(
            xsb + (size_t)xs * N_NODES * 128, wp2,
            p2 + (size_t)xs * N_NODES * 256, N_NODES, 256, 128);

    edge_pass2<<<dim3(E_ALL / 8, 2), 256>>>(el, eln, et, etn, a2_o);
    node_final1<<<dim3((N_NODES + 7) / 8, 2), 256>>>(We, be, qe);
    calc_beta<<<1, 1>>>();
    combine<<<(N_NODES * OUTF + 255) / 256, 256>>>(out);
}